// round 6
// baseline (speedup 1.0000x reference)
#include <cuda_runtime.h>
#include <cuda_bf16.h>

// Problem constants (fixed by reference):
//   N = 2048 languages, D = 64 embedding dim, V = 2048 vocab
#define N_LANG 2048
#define D_EMB  64
#define V_VOC  2048
#define TI     8      // i-rows per block in the pair kernel

typedef unsigned long long ull;

// ---------------- device scratch (static: allocation-free) ----------------
__device__ float  g_combined[V_VOC * V_VOC];           // 16 MB: 0.5*(tree + map/largest)
__device__ float2 g_ETp[(D_EMB / 2) * N_LANG];         // 512 KB: packed transposed embeddings
__device__ unsigned int       g_max_bits;
__device__ double             g_sum;
__device__ unsigned long long g_cnt;

// ---------------- packed fp32x2 helper ----------------
__device__ __forceinline__ ull f32x2_add(ull a, ull b) {
    ull r;
    asm("add.rn.f32x2 %0, %1, %2;" : "=l"(r) : "l"(a), "l"(b));
    return r;
}

// ---------------- kernel 0: reset accumulators ----------------
__global__ void init_kernel() {
    g_max_bits = 0u;
    g_sum = 0.0;
    g_cnt = 0ull;
}

// ---------------- kernel 1: largest = max(map_dist) ----------------
// map values are >= 0 (avg of two uniforms), so uint-bit atomicMax is valid.
__global__ void max_kernel(const float4* __restrict__ map4) {
    int idx = blockIdx.x * blockDim.x + threadIdx.x;
    float4 v = map4[idx];
    float m = fmaxf(fmaxf(v.x, v.y), fmaxf(v.z, v.w));
#pragma unroll
    for (int o = 16; o; o >>= 1) m = fmaxf(m, __shfl_xor_sync(0xffffffffu, m, o));
    __shared__ float sm[8];
    int w = threadIdx.x >> 5;
    if ((threadIdx.x & 31) == 0) sm[w] = m;
    __syncthreads();
    if (threadIdx.x == 0) {
        float bm = sm[0];
#pragma unroll
        for (int i = 1; i < 8; i++) bm = fmaxf(bm, sm[i]);
        atomicMax(&g_max_bits, __float_as_uint(bm));
    }
}

// ---------------- kernel 2: combined = 0.5*(tree + map/largest) ----------------
__global__ void combine_kernel(const float4* __restrict__ tree4,
                               const float4* __restrict__ map4) {
    int idx = blockIdx.x * blockDim.x + threadIdx.x;
    float inv = 1.0f / __uint_as_float(g_max_bits);
    float4 t = tree4[idx];
    float4 m = map4[idx];
    float4 c;
    c.x = 0.5f * (t.x + m.x * inv);
    c.y = 0.5f * (t.y + m.y * inv);
    c.z = 0.5f * (t.z + m.z * inv);
    c.w = 0.5f * (t.w + m.w * inv);
    reinterpret_cast<float4*>(g_combined)[idx] = c;
}

// ---------------- kernel 3: transpose embeddings into packed float2 ----------------
// g_ETp[dp * N + j] = (E[j][2dp], E[j][2dp+1])
__global__ void transpose_kernel(const float* __restrict__ E) {
    int idx = blockIdx.x * blockDim.x + threadIdx.x;   // 0 .. N*D/2-1
    int dp = idx >> 11;        // / N_LANG
    int j  = idx & (N_LANG - 1);
    g_ETp[idx] = make_float2(E[j * D_EMB + 2 * dp], E[j * D_EMB + 2 * dp + 1]);
}

// ---------------- kernel 4: main pair kernel ----------------
// Block: TI=8 consecutive i-rows x all 2048 j. 256 threads = 8 warps;
// lanes along j (32 j per warp-chunk), warp strides chunks by 8.
// E_j: register-resident packed f32x2 (coalesced LDG.64 from g_ETp), reused over 8 i.
// E_i: negated, in smem, broadcast LDS.128.
// combined rows for the block's 8 ids staged in smem (gather becomes LDS).
__global__ void __launch_bounds__(256, 2)
pair_kernel(const int* __restrict__ ids) {
    extern __shared__ float smem[];
    float* s_comb  = smem;                          // TI * V floats (64 KB)
    float* s_negEi = smem + TI * V_VOC;             // TI * D floats (2 KB)
    int*   s_idi   = (int*)(s_negEi + TI * D_EMB);  // TI ints

    const int i0 = blockIdx.x * TI;
    const int tid = threadIdx.x;

    if (tid < TI) s_idi[tid] = ids[i0 + tid];
    if (tid < TI * D_EMB / 4) {
        float4 v = reinterpret_cast<const float4*>(g_ETp /*unused*/) ? make_float4(0,0,0,0) : make_float4(0,0,0,0);
        (void)v;
    }
    __syncthreads();

    // stage negated E_i rows (read original row-major E via g_ETp is transposed;
    // easier: reconstruct from ETp? No — read straight from ETp columns is strided.
    // We kept the original E pointer unnecessary; read from g_ETp transposed instead:
    // s_negEi[il*D + 2dp(+1)] = -g_ETp[dp*N + (i0+il)]
    if (tid < TI * (D_EMB / 2)) {
        int il = tid / (D_EMB / 2);
        int dp = tid % (D_EMB / 2);
        float2 v = g_ETp[dp * N_LANG + (i0 + il)];
        s_negEi[il * D_EMB + 2 * dp]     = -v.x;
        s_negEi[il * D_EMB + 2 * dp + 1] = -v.y;
    }
    __syncthreads();   // s_idi ready for combined staging

    // stage combined rows: 8 rows * 2048 floats = 4096 float4, 16 per thread
#pragma unroll
    for (int r = 0; r < 16; r++) {
        int f4  = r * 256 + tid;        // 0..4095
        int il  = f4 >> 9;              // / 512
        int col = f4 & 511;
        reinterpret_cast<float4*>(s_comb)[f4] =
            reinterpret_cast<const float4*>(g_combined)[s_idi[il] * (V_VOC / 4) + col];
    }
    __syncthreads();

    int idi[TI];
#pragma unroll
    for (int il = 0; il < TI; il++) idi[il] = s_idi[il];

    const int warp = tid >> 5;
    const int lane = tid & 31;
    float    fsum = 0.0f;
    unsigned cnt  = 0;
    const ull ABSM = 0x7FFFFFFF7FFFFFFFull;

    for (int c = warp; c < N_LANG / 32; c += 8) {
        const int j   = c * 32 + lane;
        const int idj = __ldg(&ids[j]);

        ull ej[D_EMB / 2];
#pragma unroll
        for (int dp = 0; dp < D_EMB / 2; dp++) {
            float2 v = g_ETp[dp * N_LANG + j];   // coalesced LDG.64
            union { float2 f; ull u; } cv;
            cv.f = v;
            ej[dp] = cv.u;
        }

#pragma unroll
        for (int il = 0; il < TI; il++) {
            ull a0 = 0, a1 = 0, a2 = 0, a3 = 0;
            const ulonglong2* ei =
                reinterpret_cast<const ulonglong2*>(s_negEi + il * D_EMB);
#pragma unroll
            for (int q = 0; q < D_EMB / 4; q++) {
                ulonglong2 e = ei[q];               // broadcast LDS.128
                ull d0 = f32x2_add(ej[2 * q],     e.x) & ABSM;
                ull d1 = f32x2_add(ej[2 * q + 1], e.y) & ABSM;
                if (q & 1) { a2 = f32x2_add(a2, d0); a3 = f32x2_add(a3, d1); }
                else       { a0 = f32x2_add(a0, d0); a1 = f32x2_add(a1, d1); }
            }
            a0 = f32x2_add(a0, a2);
            a1 = f32x2_add(a1, a3);
            a0 = f32x2_add(a0, a1);
            union { ull u; float2 f; } cv;
            cv.u = a0;
            float emb = (cv.f.x + cv.f.y) * (1.0f / 64.0f);
            float cm  = s_comb[il * V_VOC + idj];   // smem gather
            if (idi[il] != idj) {
                fsum += fabsf(emb - cm);
                cnt++;
            }
        }
    }

    // block reduction -> global double accumulator
#pragma unroll
    for (int o = 16; o; o >>= 1) {
        fsum += __shfl_down_sync(0xffffffffu, fsum, o);
        cnt  += __shfl_down_sync(0xffffffffu, cnt, o);
    }
    __shared__ float    rs[8];
    __shared__ unsigned rc[8];
    if (lane == 0) { rs[warp] = fsum; rc[warp] = cnt; }
    __syncthreads();
    if (tid == 0) {
        float fs = 0.0f;
        unsigned cc = 0;
#pragma unroll
        for (int w = 0; w < 8; w++) { fs += rs[w]; cc += rc[w]; }
        atomicAdd(&g_sum, (double)fs);
        atomicAdd(&g_cnt, (unsigned long long)cc);
    }
}

// ---------------- kernel 5: finalize ----------------
__global__ void finalize_kernel(float* __restrict__ out) {
    out[0] = (float)(g_sum / (double)g_cnt);
}

// ---------------- launch ----------------
extern "C" void kernel_launch(void* const* d_in, const int* in_sizes, int n_in,
                              void* d_out, int out_size) {
    // Robust input mapping by element counts:
    //   ids: 2048 (int32), emb: 131072 (f32), tree/map: 4194304 each (f32, in order)
    const int*   ids  = nullptr;
    const float* E    = nullptr;
    const float* tree = nullptr;
    const float* mapd = nullptr;
    for (int i = 0; i < n_in; i++) {
        int sz = in_sizes[i];
        if (sz == N_LANG)              ids = (const int*)d_in[i];
        else if (sz == N_LANG * D_EMB) E   = (const float*)d_in[i];
        else if (sz == V_VOC * V_VOC) {
            if (!tree) tree = (const float*)d_in[i];
            else       mapd = (const float*)d_in[i];
        }
    }
    float* out = (float*)d_out;

    const int SMEM_BYTES = (TI * V_VOC + TI * D_EMB + 16) * (int)sizeof(float);
    cudaFuncSetAttribute(pair_kernel,
                         cudaFuncAttributeMaxDynamicSharedMemorySize, SMEM_BYTES);

    init_kernel<<<1, 1>>>();
    max_kernel<<<(V_VOC * V_VOC / 4) / 256, 256>>>((const float4*)mapd);
    combine_kernel<<<(V_VOC * V_VOC / 4) / 256, 256>>>((const float4*)tree,
                                                       (const float4*)mapd);
    transpose_kernel<<<(N_LANG * D_EMB / 2) / 256, 256>>>(E);
    pair_kernel<<<N_LANG / TI, 256, SMEM_BYTES>>>(ids);
    finalize_kernel<<<1, 1>>>(out);
}

// round 10
// speedup vs baseline: 1.0131x; 1.0131x over previous
#include <cuda_runtime.h>
#include <cuda_bf16.h>

// N = 2048 languages, D = 64, V = 2048
#define N_LANG 2048
#define D_EMB  64
#define V_VOC  2048

typedef unsigned long long ull;

// ---------------- device state (zero-init; finalize resets for next replay) ----
__device__ unsigned int       g_max_bits;
__device__ double             g_sum;
__device__ unsigned long long g_cnt;

// ---------------- packed fp32x2 add ----------------
__device__ __forceinline__ ull f32x2_add(ull a, ull b) {
    ull r;
    asm("add.rn.f32x2 %0, %1, %2;" : "=l"(r) : "l"(a), "l"(b));
    return r;
}

// ---------------- kernel 1: largest = max(map_dist) ----------------
// map values >= 0 (avg of two uniforms) so uint-bit atomicMax is order-correct.
__global__ void max_kernel(const float4* __restrict__ map4) {
    int idx = blockIdx.x * blockDim.x + threadIdx.x;   // 0 .. 524287
    float4 v = map4[idx];
    float4 w = map4[idx + (V_VOC * V_VOC / 8)];
    float m = fmaxf(fmaxf(fmaxf(v.x, v.y), fmaxf(v.z, v.w)),
                    fmaxf(fmaxf(w.x, w.y), fmaxf(w.z, w.w)));
#pragma unroll
    for (int o = 16; o; o >>= 1) m = fmaxf(m, __shfl_xor_sync(0xffffffffu, m, o));
    __shared__ float sm[8];
    int wp = threadIdx.x >> 5;
    if ((threadIdx.x & 31) == 0) sm[wp] = m;
    __syncthreads();
    if (threadIdx.x == 0) {
        float bm = sm[0];
#pragma unroll
        for (int i = 1; i < 8; i++) bm = fmaxf(bm, sm[i]);
        atomicMax(&g_max_bits, __float_as_uint(bm));
    }
}

// ---------------- kernel 2: triangular pair kernel ----------------
// Symmetry: answer = sum_{i<j} |emb - metric| * [id_i != id_j] / count_{i<j}
// (the symmetric factor 2 cancels between numerator and denominator).
//
// Block b owns two 4-row i-tiles: tA = b (rows 4b..4b+3) and tB = 511-b
// (rows 2044-4b .. 2047-4b). Triangular j-spans sum to ~const => balanced.
// Per block smem: 8 combined metric rows (fused 0.5*(tree + map*inv) during
// staging) + 8 negated E_i rows. E_j read per-lane as 16x LDG.128 (100%
// sector efficiency), register-resident, reused across up to 8 i-rows.
__global__ void __launch_bounds__(256, 2)
pair_kernel(const int* __restrict__ ids, const float* __restrict__ E,
            const float4* __restrict__ tree4, const float4* __restrict__ map4) {
    extern __shared__ float smem[];
    float* s_comb  = smem;                           // 8 * 2048 floats (64 KB)
    float* s_negEi = smem + 8 * V_VOC;               // 8 * 64 floats  (2 KB)
    int*   s_id    = (int*)(s_negEi + 8 * D_EMB);    // 8 ints

    const int b   = blockIdx.x;
    const int i0A = 4 * b;
    const int i0B = 2044 - 4 * b;
    const int tid = threadIdx.x;

    if (tid < 8) {
        int i = (tid < 4) ? (i0A + tid) : (i0B + tid - 4);
        s_id[tid] = ids[i];
    }
    __syncthreads();

    const float inv = 1.0f / __uint_as_float(g_max_bits);

    // Stage combined rows: 8 rows * 512 float4 = 4096 float4, 16 per thread.
    float4* s_comb4 = (float4*)s_comb;
#pragma unroll
    for (int r = 0; r < 16; r++) {
        int f4  = r * 256 + tid;
        int row = f4 >> 9;
        int col = f4 & 511;
        int id  = s_id[row];
        float4 t = tree4[id * (V_VOC / 4) + col];
        float4 m = map4[id * (V_VOC / 4) + col];
        float4 c;
        c.x = 0.5f * (t.x + m.x * inv);
        c.y = 0.5f * (t.y + m.y * inv);
        c.z = 0.5f * (t.z + m.z * inv);
        c.w = 0.5f * (t.w + m.w * inv);
        s_comb4[f4] = c;
    }

    // Stage negated E_i rows straight from row-major E (coalesced float4).
    if (tid < 8 * (D_EMB / 4)) {
        int row = tid >> 4;
        int q   = tid & 15;
        int i   = (row < 4) ? (i0A + row) : (i0B + row - 4);
        float4 v = ((const float4*)E)[i * (D_EMB / 4) + q];
        float4 n;
        n.x = -v.x; n.y = -v.y; n.z = -v.z; n.w = -v.w;
        ((float4*)s_negEi)[row * (D_EMB / 4) + q] = n;
    }
    __syncthreads();

    const int warp = tid >> 5;
    const int lane = tid & 31;
    const int c0A  = i0A >> 5;
    const int c0B  = i0B >> 5;   // always > c0A (i0A <= 1020 < 1024 <= i0B)

    int iA[4], iB[4], idA[4], idB[4];
#pragma unroll
    for (int il = 0; il < 4; il++) {
        iA[il]  = i0A + il;      iB[il]  = i0B + il;
        idA[il] = s_id[il];      idB[il] = s_id[4 + il];
    }

    float    fsum = 0.0f;
    unsigned cnt  = 0;
    const ull ABSM = 0x7FFFFFFF7FFFFFFFull;

    for (int c = c0A + warp; c < N_LANG / 32; c += 8) {
        const int j   = c * 32 + lane;
        const int idj = __ldg(&ids[j]);

        // E_j: 64 floats = 16 LDG.128, fully sector-efficient per lane.
        ulonglong2 ej[16];
        const ulonglong2* Ej = ((const ulonglong2*)E) + j * 16;
#pragma unroll
        for (int q = 0; q < 16; q++) ej[q] = Ej[q];

        // Tile A rows (always active for c >= c0A)
#pragma unroll
        for (int il = 0; il < 4; il++) {
            const ulonglong2* ei = (const ulonglong2*)(s_negEi + il * D_EMB);
            ull a0 = 0, a1 = 0, a2 = 0, a3 = 0;
#pragma unroll
            for (int q = 0; q < 16; q++) {
                ulonglong2 e = ei[q];               // broadcast LDS.128
                ull d0 = f32x2_add(ej[q].x, e.x) & ABSM;
                ull d1 = f32x2_add(ej[q].y, e.y) & ABSM;
                if (q & 1) { a2 = f32x2_add(a2, d0); a3 = f32x2_add(a3, d1); }
                else       { a0 = f32x2_add(a0, d0); a1 = f32x2_add(a1, d1); }
            }
            a0 = f32x2_add(a0, a2);
            a1 = f32x2_add(a1, a3);
            a0 = f32x2_add(a0, a1);
            union { ull u; float2 f; } cv; cv.u = a0;
            float emb = (cv.f.x + cv.f.y) * (1.0f / 64.0f);
            float cm  = s_comb[il * V_VOC + idj];
            if (j > iA[il] && idA[il] != idj) { fsum += fabsf(emb - cm); cnt++; }
        }

        // Tile B rows (active only in the top chunk region) — reuses ej regs.
        if (c >= c0B) {
#pragma unroll
            for (int il = 0; il < 4; il++) {
                const ulonglong2* ei = (const ulonglong2*)(s_negEi + (4 + il) * D_EMB);
                ull a0 = 0, a1 = 0, a2 = 0, a3 = 0;
#pragma unroll
                for (int q = 0; q < 16; q++) {
                    ulonglong2 e = ei[q];
                    ull d0 = f32x2_add(ej[q].x, e.x) & ABSM;
                    ull d1 = f32x2_add(ej[q].y, e.y) & ABSM;
                    if (q & 1) { a2 = f32x2_add(a2, d0); a3 = f32x2_add(a3, d1); }
                    else       { a0 = f32x2_add(a0, d0); a1 = f32x2_add(a1, d1); }
                }
                a0 = f32x2_add(a0, a2);
                a1 = f32x2_add(a1, a3);
                a0 = f32x2_add(a0, a1);
                union { ull u; float2 f; } cv; cv.u = a0;
                float emb = (cv.f.x + cv.f.y) * (1.0f / 64.0f);
                float cm  = s_comb[(4 + il) * V_VOC + idj];
                if (j > iB[il] && idB[il] != idj) { fsum += fabsf(emb - cm); cnt++; }
            }
        }
    }

    // Block reduction -> global double accumulator.
#pragma unroll
    for (int o = 16; o; o >>= 1) {
        fsum += __shfl_down_sync(0xffffffffu, fsum, o);
        cnt  += __shfl_down_sync(0xffffffffu, cnt, o);
    }
    __shared__ float    rs[8];
    __shared__ unsigned rc[8];
    if (lane == 0) { rs[warp] = fsum; rc[warp] = cnt; }
    __syncthreads();
    if (tid == 0) {
        float fs = 0.0f;
        unsigned cc = 0;
#pragma unroll
        for (int w = 0; w < 8; w++) { fs += rs[w]; cc += rc[w]; }
        atomicAdd(&g_sum, (double)fs);
        atomicAdd(&g_cnt, (unsigned long long)cc);
    }
}

// ---------------- kernel 3: finalize (write out, then reset for next replay) --
__global__ void finalize_kernel(float* __restrict__ out) {
    out[0] = (float)(g_sum / (double)g_cnt);
    g_sum = 0.0;
    g_cnt = 0ull;
    g_max_bits = 0u;
}

// ---------------- launch ----------------
extern "C" void kernel_launch(void* const* d_in, const int* in_sizes, int n_in,
                              void* d_out, int out_size) {
    // Map inputs by element count: ids 2048 (i32), E 131072 (f32),
    // tree then map 4194304 each (f32, metadata order).
    const int*   ids  = nullptr;
    const float* E    = nullptr;
    const float* tree = nullptr;
    const float* mapd = nullptr;
    for (int i = 0; i < n_in; i++) {
        int sz = in_sizes[i];
        if (sz == N_LANG)              ids = (const int*)d_in[i];
        else if (sz == N_LANG * D_EMB) E   = (const float*)d_in[i];
        else if (sz == V_VOC * V_VOC) {
            if (!tree) tree = (const float*)d_in[i];
            else       mapd = (const float*)d_in[i];
        }
    }
    float* out = (float*)d_out;

    const int SMEM_BYTES = (8 * V_VOC + 8 * D_EMB + 8) * (int)sizeof(float);
    cudaFuncSetAttribute(pair_kernel,
                         cudaFuncAttributeMaxDynamicSharedMemorySize, SMEM_BYTES);

    max_kernel<<<(V_VOC * V_VOC / 8) / 256, 256>>>((const float4*)mapd);
    pair_kernel<<<256, 256, SMEM_BYTES>>>(ids, E, (const float4*)tree,
                                          (const float4*)mapd);
    finalize_kernel<<<1, 1>>>(out);
}

// round 12
// speedup vs baseline: 1.3347x; 1.3174x over previous
#include <cuda_runtime.h>
#include <cuda_bf16.h>

// N = 2048 languages, D = 64, V = 2048
#define N_LANG 2048
#define D_EMB  64
#define V_VOC  2048

typedef unsigned long long ull;

// ---------------- device state ----------------
__device__ float2 g_ETp[(D_EMB / 2) * N_LANG];   // 512 KB transposed packed E
__device__ unsigned int       g_max_bits;
__device__ double             g_sum;
__device__ unsigned long long g_cnt;

__device__ __forceinline__ ull f32x2_add(ull a, ull b) {
    ull r;
    asm("add.rn.f32x2 %0, %1, %2;" : "=l"(r) : "l"(a), "l"(b));
    return r;
}

// ---------------- kernel 1: tiled transpose E -> g_ETp ----------------
// g_ETp[dp * N + j] = (E[j][2dp], E[j][2dp+1]).  Coalesced read AND write.
__global__ void transpose_kernel(const float4* __restrict__ E4) {
    __shared__ float s[32][66];          // 32 j-rows x 64 dims (+2 pad)
    const int b = blockIdx.x;            // 64 blocks, 32 j each
    const int t = threadIdx.x;           // 256 threads
#pragma unroll
    for (int r = 0; r < 2; r++) {
        int idx = r * 256 + t;
        int jl  = idx >> 4;              // 0..31
        int q   = idx & 15;              // 0..15 float4 within row
        float4 v = E4[(b * 32 + jl) * 16 + q];
        s[jl][q * 4 + 0] = v.x;
        s[jl][q * 4 + 1] = v.y;
        s[jl][q * 4 + 2] = v.z;
        s[jl][q * 4 + 3] = v.w;
    }
    __syncthreads();
    const int jl = t & 31;
#pragma unroll
    for (int k = 0; k < 4; k++) {
        int dp = (t >> 5) + 8 * k;       // 0..31
        g_ETp[dp * N_LANG + b * 32 + jl] = make_float2(s[jl][2 * dp], s[jl][2 * dp + 1]);
    }
}

// ---------------- kernel 2: largest = max(map_dist), high-MLP ----------------
// map values >= 0, so uint-bit atomicMax is order-correct.
__global__ void max_kernel(const float4* __restrict__ map4) {
    const int idx = blockIdx.x * blockDim.x + threadIdx.x;   // 0 .. 131071
    float m = 0.0f;
#pragma unroll
    for (int k = 0; k < 8; k++) {                            // 8 front-batched loads
        float4 v = map4[idx + k * 131072];
        m = fmaxf(m, fmaxf(fmaxf(v.x, v.y), fmaxf(v.z, v.w)));
    }
#pragma unroll
    for (int o = 16; o; o >>= 1) m = fmaxf(m, __shfl_xor_sync(0xffffffffu, m, o));
    __shared__ float sm[8];
    int wp = threadIdx.x >> 5;
    if ((threadIdx.x & 31) == 0) sm[wp] = m;
    __syncthreads();
    if (threadIdx.x == 0) {
        float bm = sm[0];
#pragma unroll
        for (int i = 1; i < 8; i++) bm = fmaxf(bm, sm[i]);
        atomicMax(&g_max_bits, __float_as_uint(bm));
    }
}

// ---------------- kernel 3: triangular pair kernel ----------------
// answer = sum_{i<j} |emb - metric| * [id_i != id_j] / count_{i<j}  (factor 2 cancels)
// Grid 512: pair p = bx>>1 owns tiles tA = rows 4p..4p+3 and tB = rows 2044-4p..2047-4p
// (triangular spans sum ~const -> balanced); h = bx&1 splits the chunk span so ~444
// CTAs are resident at occupancy 3 (24 warps/SM).
// E_j: coalesced LDG.64 from transposed g_ETp (2 lines/load), register-resident in
// D-quarters, reused across up to 8 i-rows. Combined metric rows fused
// 0.5*(tree + map*inv) into smem during staging. E_i negated in smem (LDS.128 bcast).
__global__ void __launch_bounds__(256, 3)
pair_kernel(const int* __restrict__ ids, const float* __restrict__ E,
            const float4* __restrict__ tree4, const float4* __restrict__ map4) {
    extern __shared__ float smem[];
    float* s_comb  = smem;                           // 8 * 2048 floats (64 KB)
    float* s_negEi = smem + 8 * V_VOC;               // 8 * 64 floats  (2 KB)
    int*   s_id    = (int*)(s_negEi + 8 * D_EMB);    // 8 ints

    const int p   = blockIdx.x >> 1;
    const int h   = blockIdx.x & 1;
    const int i0A = 4 * p;
    const int i0B = 2044 - 4 * p;
    const int tid = threadIdx.x;

    if (tid < 8) {
        int i = (tid < 4) ? (i0A + tid) : (i0B + tid - 4);
        s_id[tid] = ids[i];
    }
    __syncthreads();

    const float inv = 1.0f / __uint_as_float(g_max_bits);

    // Stage combined rows: 8 rows * 512 float4 = 4096 float4, 16 per thread.
    float4* s_comb4 = (float4*)s_comb;
#pragma unroll
    for (int r = 0; r < 16; r++) {
        int f4  = r * 256 + tid;
        int row = f4 >> 9;
        int col = f4 & 511;
        int id  = s_id[row];
        float4 t = tree4[id * (V_VOC / 4) + col];
        float4 m = map4[id * (V_VOC / 4) + col];
        float4 c;
        c.x = 0.5f * (t.x + m.x * inv);
        c.y = 0.5f * (t.y + m.y * inv);
        c.z = 0.5f * (t.z + m.z * inv);
        c.w = 0.5f * (t.w + m.w * inv);
        s_comb4[f4] = c;
    }

    // Stage negated E_i rows from row-major E (coalesced float4).
    if (tid < 8 * (D_EMB / 4)) {
        int row = tid >> 4;
        int q   = tid & 15;
        int i   = (row < 4) ? (i0A + row) : (i0B + row - 4);
        float4 v = ((const float4*)E)[i * (D_EMB / 4) + q];
        float4 n;
        n.x = -v.x; n.y = -v.y; n.z = -v.z; n.w = -v.w;
        ((float4*)s_negEi)[row * (D_EMB / 4) + q] = n;
    }
    __syncthreads();

    const int warp = tid >> 5;
    const int lane = tid & 31;
    const int c0A  = i0A >> 5;
    const int c0B  = i0B >> 5;

    int iA[4], iB[4], idA[4], idB[4];
#pragma unroll
    for (int il = 0; il < 4; il++) {
        iA[il]  = i0A + il;      iB[il]  = i0B + il;
        idA[il] = s_id[il];      idB[il] = s_id[4 + il];
    }

    float    fsum = 0.0f;
    unsigned cnt  = 0;
    const ull ABSM = 0x7FFFFFFF7FFFFFFFull;

    for (int c = c0A + 2 * warp + h; c < N_LANG / 32; c += 16) {
        const int j    = c * 32 + lane;
        const int idj  = __ldg(&ids[j]);
        const bool hasB = (c >= c0B);

        ull acc[8];
#pragma unroll
        for (int r = 0; r < 8; r++) acc[r] = 0;

#pragma unroll
        for (int quar = 0; quar < 4; quar++) {
            // E_j quarter: 8 coalesced LDG.64 (lanes consecutive in j).
            ull ej[8];
#pragma unroll
            for (int q = 0; q < 8; q++) {
                float2 v = g_ETp[(quar * 8 + q) * N_LANG + j];
                union { float2 f; ull u; } cv; cv.f = v;
                ej[q] = cv.u;
            }
            // Tile A rows: always active.
#pragma unroll
            for (int il = 0; il < 4; il++) {
                const ulonglong2* ei2 =
                    (const ulonglong2*)(s_negEi + il * D_EMB + quar * 16);
                ull a = acc[il];
#pragma unroll
                for (int q2 = 0; q2 < 4; q2++) {
                    ulonglong2 e = ei2[q2];                  // broadcast LDS.128
                    a = f32x2_add(a, f32x2_add(ej[2 * q2],     e.x) & ABSM);
                    a = f32x2_add(a, f32x2_add(ej[2 * q2 + 1], e.y) & ABSM);
                }
                acc[il] = a;
            }
            // Tile B rows: top region only; reuses ej registers.
            if (hasB) {
#pragma unroll
                for (int il = 0; il < 4; il++) {
                    const ulonglong2* ei2 =
                        (const ulonglong2*)(s_negEi + (4 + il) * D_EMB + quar * 16);
                    ull a = acc[4 + il];
#pragma unroll
                    for (int q2 = 0; q2 < 4; q2++) {
                        ulonglong2 e = ei2[q2];
                        a = f32x2_add(a, f32x2_add(ej[2 * q2],     e.x) & ABSM);
                        a = f32x2_add(a, f32x2_add(ej[2 * q2 + 1], e.y) & ABSM);
                    }
                    acc[4 + il] = a;
                }
            }
        }

        // Epilogue per row.
#pragma unroll
        for (int il = 0; il < 4; il++) {
            union { ull u; float2 f; } cv; cv.u = acc[il];
            float emb = (cv.f.x + cv.f.y) * (1.0f / 64.0f);
            float cm  = s_comb[il * V_VOC + idj];
            if (j > iA[il] && idA[il] != idj) { fsum += fabsf(emb - cm); cnt++; }
        }
        if (hasB) {
#pragma unroll
            for (int il = 0; il < 4; il++) {
                union { ull u; float2 f; } cv; cv.u = acc[4 + il];
                float emb = (cv.f.x + cv.f.y) * (1.0f / 64.0f);
                float cm  = s_comb[(4 + il) * V_VOC + idj];
                if (j > iB[il] && idB[il] != idj) { fsum += fabsf(emb - cm); cnt++; }
            }
        }
    }

    // Block reduction -> global double accumulator.
#pragma unroll
    for (int o = 16; o; o >>= 1) {
        fsum += __shfl_down_sync(0xffffffffu, fsum, o);
        cnt  += __shfl_down_sync(0xffffffffu, cnt, o);
    }
    __shared__ float    rs[8];
    __shared__ unsigned rc[8];
    if (lane == 0) { rs[warp] = fsum; rc[warp] = cnt; }
    __syncthreads();
    if (tid == 0) {
        float fs = 0.0f;
        unsigned cc = 0;
#pragma unroll
        for (int w = 0; w < 8; w++) { fs += rs[w]; cc += rc[w]; }
        atomicAdd(&g_sum, (double)fs);
        atomicAdd(&g_cnt, (unsigned long long)cc);
    }
}

// ---------------- kernel 4: finalize (write, then reset for next replay) ------
__global__ void finalize_kernel(float* __restrict__ out) {
    out[0] = (float)(g_sum / (double)g_cnt);
    g_sum = 0.0;
    g_cnt = 0ull;
    g_max_bits = 0u;
}

// ---------------- launch ----------------
extern "C" void kernel_launch(void* const* d_in, const int* in_sizes, int n_in,
                              void* d_out, int out_size) {
    const int*   ids  = nullptr;
    const float* E    = nullptr;
    const float* tree = nullptr;
    const float* mapd = nullptr;
    for (int i = 0; i < n_in; i++) {
        int sz = in_sizes[i];
        if (sz == N_LANG)              ids = (const int*)d_in[i];
        else if (sz == N_LANG * D_EMB) E   = (const float*)d_in[i];
        else if (sz == V_VOC * V_VOC) {
            if (!tree) tree = (const float*)d_in[i];
            else       mapd = (const float*)d_in[i];
        }
    }
    float* out = (float*)d_out;

    const int SMEM_BYTES = (8 * V_VOC + 8 * D_EMB + 8) * (int)sizeof(float);
    cudaFuncSetAttribute(pair_kernel,
                         cudaFuncAttributeMaxDynamicSharedMemorySize, SMEM_BYTES);

    transpose_kernel<<<N_LANG / 32, 256>>>((const float4*)E);
    max_kernel<<<512, 256>>>((const float4*)mapd);
    pair_kernel<<<512, 256, SMEM_BYTES>>>(ids, E, (const float4*)tree,
                                          (const float4*)mapd);
    finalize_kernel<<<1, 1>>>(out);
}

// round 13
// speedup vs baseline: 1.4741x; 1.1045x over previous
#include <cuda_runtime.h>
#include <cuda_bf16.h>

// N = 2048 languages, D = 64, V = 2048
#define N_LANG 2048
#define D_EMB  64
#define V_VOC  2048
#define TIH    8       // rows per tile; a block owns two tiles = 16 i-rows
#define NPAIR  128     // pair-kernel grid

typedef unsigned long long ull;

// ---------------- device state (zero-init; pair kernel resets at end) --------
__device__ float2 g_ETp[(D_EMB / 2) * N_LANG];   // 512 KB transposed packed E
__device__ unsigned int       g_max_bits;
__device__ double             g_sum;
__device__ unsigned long long g_cnt;
__device__ unsigned int       g_done;

__device__ __forceinline__ ull f32x2_add(ull a, ull b) {
    ull r;
    asm("add.rn.f32x2 %0, %1, %2;" : "=l"(r) : "l"(a), "l"(b));
    return r;
}

// ---------------- kernel 1: fused prep (transpose || max) --------------------
// Blocks 0..63: tiled transpose E -> g_ETp (coalesced read AND write).
// Blocks 64..575: max(map_dist) with MLP-8 front-batched loads.
// map values >= 0 (avg of two uniforms) so uint-bit atomicMax is order-correct.
__global__ void prep_kernel(const float4* __restrict__ E4,
                            const float4* __restrict__ map4) {
    __shared__ float s[32][66];
    __shared__ float sm[8];
    const int t = threadIdx.x;

    if (blockIdx.x < 64) {
        const int b = blockIdx.x;            // 32 j-rows per block
#pragma unroll
        for (int r = 0; r < 2; r++) {
            int idx = r * 256 + t;
            int jl  = idx >> 4;              // 0..31
            int q   = idx & 15;              // float4 within row
            float4 v = E4[(b * 32 + jl) * 16 + q];
            s[jl][q * 4 + 0] = v.x;
            s[jl][q * 4 + 1] = v.y;
            s[jl][q * 4 + 2] = v.z;
            s[jl][q * 4 + 3] = v.w;
        }
        __syncthreads();
        const int jl = t & 31;
#pragma unroll
        for (int k = 0; k < 4; k++) {
            int dp = (t >> 5) + 8 * k;       // 0..31
            g_ETp[dp * N_LANG + b * 32 + jl] =
                make_float2(s[jl][2 * dp], s[jl][2 * dp + 1]);
        }
    } else {
        const int idx = (blockIdx.x - 64) * 256 + t;   // 0 .. 131071
        float m = 0.0f;
#pragma unroll
        for (int k = 0; k < 8; k++) {
            float4 v = map4[idx + k * 131072];
            m = fmaxf(m, fmaxf(fmaxf(v.x, v.y), fmaxf(v.z, v.w)));
        }
#pragma unroll
        for (int o = 16; o; o >>= 1) m = fmaxf(m, __shfl_xor_sync(0xffffffffu, m, o));
        int wp = t >> 5;
        if ((t & 31) == 0) sm[wp] = m;
        __syncthreads();
        if (t == 0) {
            float bm = sm[0];
#pragma unroll
            for (int i = 1; i < 8; i++) bm = fmaxf(bm, sm[i]);
            atomicMax(&g_max_bits, __float_as_uint(bm));
        }
    }
}

// ---------------- kernel 2: triangular pair kernel + fused finalize ----------
// answer = sum_{i<j} |emb - metric| * [id_i != id_j] / count_{i<j} (factor 2 cancels).
// Block p owns tiles tA = p (rows 8p..8p+7) and tB = 255-p (rows 2040-8p..2047-8p):
// triangular spans sum ~const -> 128 balanced blocks, one wave, occupancy 1.
// ej: coalesced LDG.64 from transposed g_ETp, register-resident per D-quarter,
// reused across up to 16 i-rows. Combined metric rows (0.5*(tree+map*inv)) fused
// into 128KB smem during staging. Last block writes out and resets state.
__global__ void __launch_bounds__(256, 1)
pair_kernel(const int* __restrict__ ids, const float* __restrict__ E,
            const float4* __restrict__ tree4, const float4* __restrict__ map4,
            float* __restrict__ out) {
    extern __shared__ float smem[];
    float* s_comb  = smem;                            // 16 * 2048 floats (128 KB)
    float* s_negEi = smem + 16 * V_VOC;               // 16 * 64 floats  (4 KB)
    int*   s_id    = (int*)(s_negEi + 16 * D_EMB);    // 16 ints

    const int p   = blockIdx.x;
    const int i0A = TIH * p;                  // 8p
    const int i0B = N_LANG - TIH - TIH * p;   // 2040 - 8p
    const int tid = threadIdx.x;

    if (tid < 16) {
        int i = (tid < 8) ? (i0A + tid) : (i0B + tid - 8);
        s_id[tid] = ids[i];
    }
    // Stage negated E_i rows (uses only i0A/i0B, safe before sync).
    if (tid >= 256 - 16 * 16 || true) { /* all threads used below */ }
    __syncthreads();

    const float inv = 1.0f / __uint_as_float(g_max_bits);

    // Stage combined rows: 16 rows * 512 float4 = 8192 float4, 32 per thread.
    float4* s_comb4 = (float4*)s_comb;
#pragma unroll
    for (int r = 0; r < 32; r++) {
        int f4  = r * 256 + tid;
        int row = f4 >> 9;
        int col = f4 & 511;
        int id  = s_id[row];
        float4 t = tree4[id * (V_VOC / 4) + col];
        float4 m = map4[id * (V_VOC / 4) + col];
        float4 c;
        c.x = 0.5f * (t.x + m.x * inv);
        c.y = 0.5f * (t.y + m.y * inv);
        c.z = 0.5f * (t.z + m.z * inv);
        c.w = 0.5f * (t.w + m.w * inv);
        s_comb4[f4] = c;
    }
    // Negated E_i rows: 16 rows * 16 float4 = 256 float4, 1 per thread.
    {
        int row = tid >> 4;
        int q   = tid & 15;
        int i   = (row < 8) ? (i0A + row) : (i0B + row - 8);
        float4 v = ((const float4*)E)[i * (D_EMB / 4) + q];
        float4 n;
        n.x = -v.x; n.y = -v.y; n.z = -v.z; n.w = -v.w;
        ((float4*)s_negEi)[row * (D_EMB / 4) + q] = n;
    }
    __syncthreads();

    const int warp = tid >> 5;
    const int lane = tid & 31;
    const int c0A  = i0A >> 5;
    const int c0B  = i0B >> 5;

    float    fsum = 0.0f;
    unsigned cnt  = 0;
    const ull ABSM = 0x7FFFFFFF7FFFFFFFull;

    for (int c = c0A + warp; c < N_LANG / 32; c += 8) {
        const int  j    = c * 32 + lane;
        const int  idj  = __ldg(&ids[j]);
        const bool hasB = (c >= c0B);

        ull acc[16];
#pragma unroll
        for (int r = 0; r < 16; r++) acc[r] = 0;

#pragma unroll
        for (int quar = 0; quar < 4; quar++) {
            // E_j quarter: 8 coalesced LDG.64 (lanes consecutive in j).
            ull ej[8];
#pragma unroll
            for (int q = 0; q < 8; q++) {
                float2 v = g_ETp[(quar * 8 + q) * N_LANG + j];
                union { float2 f; ull u; } cv; cv.f = v;
                ej[q] = cv.u;
            }
            // Tile A rows: always active for c >= c0A.
#pragma unroll
            for (int il = 0; il < 8; il++) {
                const ulonglong2* ei2 =
                    (const ulonglong2*)(s_negEi + il * D_EMB + quar * 16);
                ull a = acc[il];
#pragma unroll
                for (int q2 = 0; q2 < 4; q2++) {
                    ulonglong2 e = ei2[q2];                  // broadcast LDS.128
                    a = f32x2_add(a, f32x2_add(ej[2 * q2],     e.x) & ABSM);
                    a = f32x2_add(a, f32x2_add(ej[2 * q2 + 1], e.y) & ABSM);
                }
                acc[il] = a;
            }
            // Tile B rows: top region only; reuses ej registers.
            if (hasB) {
#pragma unroll
                for (int il = 0; il < 8; il++) {
                    const ulonglong2* ei2 =
                        (const ulonglong2*)(s_negEi + (8 + il) * D_EMB + quar * 16);
                    ull a = acc[8 + il];
#pragma unroll
                    for (int q2 = 0; q2 < 4; q2++) {
                        ulonglong2 e = ei2[q2];
                        a = f32x2_add(a, f32x2_add(ej[2 * q2],     e.x) & ABSM);
                        a = f32x2_add(a, f32x2_add(ej[2 * q2 + 1], e.y) & ABSM);
                    }
                    acc[8 + il] = a;
                }
            }
        }

        // Epilogue (idi re-read from smem broadcast to save registers).
#pragma unroll
        for (int il = 0; il < 8; il++) {
            union { ull u; float2 f; } cv; cv.u = acc[il];
            float emb = (cv.f.x + cv.f.y) * (1.0f / 64.0f);
            float cm  = s_comb[il * V_VOC + idj];
            if (j > i0A + il && s_id[il] != idj) { fsum += fabsf(emb - cm); cnt++; }
        }
        if (hasB) {
#pragma unroll
            for (int il = 0; il < 8; il++) {
                union { ull u; float2 f; } cv; cv.u = acc[8 + il];
                float emb = (cv.f.x + cv.f.y) * (1.0f / 64.0f);
                float cm  = s_comb[(8 + il) * V_VOC + idj];
                if (j > i0B + il && s_id[8 + il] != idj) { fsum += fabsf(emb - cm); cnt++; }
            }
        }
    }

    // Block reduction -> global double accumulator, then last-block finalize.
#pragma unroll
    for (int o = 16; o; o >>= 1) {
        fsum += __shfl_down_sync(0xffffffffu, fsum, o);
        cnt  += __shfl_down_sync(0xffffffffu, cnt, o);
    }
    __shared__ float    rs[8];
    __shared__ unsigned rc[8];
    if (lane == 0) { rs[warp] = fsum; rc[warp] = cnt; }
    __syncthreads();
    if (tid == 0) {
        float fs = 0.0f;
        unsigned cc = 0;
#pragma unroll
        for (int w = 0; w < 8; w++) { fs += rs[w]; cc += rc[w]; }
        atomicAdd(&g_sum, (double)fs);
        atomicAdd(&g_cnt, (unsigned long long)cc);
        __threadfence();
        unsigned ticket = atomicAdd(&g_done, 1u);
        if (ticket == NPAIR - 1) {
            out[0] = (float)(g_sum / (double)g_cnt);
            g_sum = 0.0;
            g_cnt = 0ull;
            g_max_bits = 0u;
            g_done = 0u;
        }
    }
}

// ---------------- launch ----------------
extern "C" void kernel_launch(void* const* d_in, const int* in_sizes, int n_in,
                              void* d_out, int out_size) {
    const int*   ids  = nullptr;
    const float* E    = nullptr;
    const float* tree = nullptr;
    const float* mapd = nullptr;
    for (int i = 0; i < n_in; i++) {
        int sz = in_sizes[i];
        if (sz == N_LANG)              ids = (const int*)d_in[i];
        else if (sz == N_LANG * D_EMB) E   = (const float*)d_in[i];
        else if (sz == V_VOC * V_VOC) {
            if (!tree) tree = (const float*)d_in[i];
            else       mapd = (const float*)d_in[i];
        }
    }
    float* out = (float*)d_out;

    const int SMEM_BYTES = (16 * V_VOC + 16 * D_EMB + 16) * (int)sizeof(float);
    cudaFuncSetAttribute(pair_kernel,
                         cudaFuncAttributeMaxDynamicSharedMemorySize, SMEM_BYTES);

    prep_kernel<<<576, 256>>>((const float4*)E, (const float4*)mapd);
    pair_kernel<<<NPAIR, 256, SMEM_BYTES>>>(ids, E, (const float4*)tree,
                                            (const float4*)mapd, out);
}

// round 14
// speedup vs baseline: 1.8485x; 1.2540x over previous
#include <cuda_runtime.h>
#include <cuda_bf16.h>

// N = 2048 languages, D = 64, V = 2048
#define N_LANG 2048
#define D_EMB  64
#define V_VOC  2048
#define NPAIR  256     // pair-kernel grid: block p owns rows 4p..4p+3 and 2044-4p..2047-4p

typedef unsigned long long ull;

// ---------------- device state (zero-init; pair kernel resets at end) --------
__device__ float2 g_ETp[(D_EMB / 2) * N_LANG];   // 512 KB transposed packed E
__device__ unsigned int       g_max_bits;
__device__ double             g_sum;
__device__ unsigned long long g_cnt;
__device__ unsigned int       g_done;

__device__ __forceinline__ ull f32x2_add(ull a, ull b) {
    ull r;
    asm("add.rn.f32x2 %0, %1, %2;" : "=l"(r) : "l"(a), "l"(b));
    return r;
}

// ---------------- kernel 1: fused prep (transpose || max) --------------------
// Blocks 0..63: tiled transpose E -> g_ETp (coalesced read AND write).
// Blocks 64..575: max(map_dist) with MLP-8 front-batched loads.
// map values >= 0 (avg of two uniforms) so uint-bit atomicMax is order-correct.
__global__ void prep_kernel(const float4* __restrict__ E4,
                            const float4* __restrict__ map4) {
    __shared__ float s[32][66];
    __shared__ float sm[8];
    const int t = threadIdx.x;

    if (blockIdx.x < 64) {
        const int b = blockIdx.x;            // 32 j-rows per block
#pragma unroll
        for (int r = 0; r < 2; r++) {
            int idx = r * 256 + t;
            int jl  = idx >> 4;
            int q   = idx & 15;
            float4 v = E4[(b * 32 + jl) * 16 + q];
            s[jl][q * 4 + 0] = v.x;
            s[jl][q * 4 + 1] = v.y;
            s[jl][q * 4 + 2] = v.z;
            s[jl][q * 4 + 3] = v.w;
        }
        __syncthreads();
        const int jl = t & 31;
#pragma unroll
        for (int k = 0; k < 4; k++) {
            int dp = (t >> 5) + 8 * k;
            g_ETp[dp * N_LANG + b * 32 + jl] =
                make_float2(s[jl][2 * dp], s[jl][2 * dp + 1]);
        }
    } else {
        const int idx = (blockIdx.x - 64) * 256 + t;   // 0 .. 131071
        float m = 0.0f;
#pragma unroll
        for (int k = 0; k < 8; k++) {
            float4 v = map4[idx + k * 131072];
            m = fmaxf(m, fmaxf(fmaxf(v.x, v.y), fmaxf(v.z, v.w)));
        }
#pragma unroll
        for (int o = 16; o; o >>= 1) m = fmaxf(m, __shfl_xor_sync(0xffffffffu, m, o));
        int wp = t >> 5;
        if ((t & 31) == 0) sm[wp] = m;
        __syncthreads();
        if (t == 0) {
            float bm = sm[0];
#pragma unroll
            for (int i = 1; i < 8; i++) bm = fmaxf(bm, sm[i]);
            atomicMax(&g_max_bits, __float_as_uint(bm));
        }
    }
}

// ---------------- kernel 2: triangular pair kernel + fused finalize ----------
// answer = sum_{i<j} |emb - metric| * [id_i != id_j] / count_{i<j} (factor 2 cancels).
// Block p owns tiles tA = rows 4p..4p+3 and tB = rows 2044-4p..2047-4p:
// triangular chunk-spans sum ~const -> 256 balanced blocks at occupancy 2.
// Each lane handles TWO consecutive j's: one LDG.128 of transposed g_ETp yields a
// dim-pair for both j's, and each LDS.128 broadcast of neg-E_i feeds both ->
// halves LDS + overhead per pair. Combined metric rows (0.5*(tree+map*inv))
// fused into 64KB smem during staging. Last block writes out and resets state.
__global__ void __launch_bounds__(256, 2)
pair_kernel(const int* __restrict__ ids, const float* __restrict__ E,
            const float4* __restrict__ tree4, const float4* __restrict__ map4,
            float* __restrict__ out) {
    extern __shared__ float smem[];
    float* s_comb  = smem;                           // 8 * 2048 floats (64 KB)
    float* s_negEi = smem + 8 * V_VOC;               // 8 * 64 floats  (2 KB)
    int*   s_id    = (int*)(s_negEi + 8 * D_EMB);    // 8 ints

    const int p   = blockIdx.x;
    const int i0A = 4 * p;
    const int i0B = N_LANG - 4 - 4 * p;   // 2044 - 4p
    const int tid = threadIdx.x;

    if (tid < 8) {
        int i = (tid < 4) ? (i0A + tid) : (i0B + tid - 4);
        s_id[tid] = ids[i];
    }
    __syncthreads();

    const float inv = 1.0f / __uint_as_float(g_max_bits);

    // Stage combined rows: 8 rows * 512 float4 = 4096 float4, 16 per thread.
    float4* s_comb4 = (float4*)s_comb;
#pragma unroll
    for (int r = 0; r < 16; r++) {
        int f4  = r * 256 + tid;
        int row = f4 >> 9;
        int col = f4 & 511;
        int id  = s_id[row];
        float4 t = tree4[id * (V_VOC / 4) + col];
        float4 m = map4[id * (V_VOC / 4) + col];
        float4 c;
        c.x = 0.5f * (t.x + m.x * inv);
        c.y = 0.5f * (t.y + m.y * inv);
        c.z = 0.5f * (t.z + m.z * inv);
        c.w = 0.5f * (t.w + m.w * inv);
        s_comb4[f4] = c;
    }
    // Negated E_i rows: 8 rows * 16 float4 = 128 float4.
    if (tid < 128) {
        int row = tid >> 4;
        int q   = tid & 15;
        int i   = (row < 4) ? (i0A + row) : (i0B + row - 4);
        float4 v = ((const float4*)E)[i * (D_EMB / 4) + q];
        float4 n;
        n.x = -v.x; n.y = -v.y; n.z = -v.z; n.w = -v.w;
        ((float4*)s_negEi)[row * (D_EMB / 4) + q] = n;
    }
    __syncthreads();

    const int warp = tid >> 5;
    const int lane = tid & 31;
    const int c0A  = i0A >> 6;            // chunks are 64 j wide
    const int c0B  = i0B >> 6;

    float    fsum = 0.0f;
    unsigned cnt  = 0;
    const ull ABSM = 0x7FFFFFFF7FFFFFFFull;
    const ulonglong2* ETp2 = (const ulonglong2*)g_ETp;

    for (int c = c0A + warp; c < N_LANG / 64; c += 8) {
        const int  j0   = c * 64 + 2 * lane;           // this lane's two j's: j0, j0+1
        const int  idj0 = __ldg(&ids[j0]);
        const int  idj1 = __ldg(&ids[j0 + 1]);
        const bool hasB = (c >= c0B);
        const int  ejb  = c * 32 + lane;               // ulonglong2 index base

        ull acc[16];                                    // [row 0..7][jslot 0..1]
#pragma unroll
        for (int r = 0; r < 16; r++) acc[r] = 0;

#pragma unroll
        for (int quar = 0; quar < 4; quar++) {
            // 8 coalesced LDG.128: dim-pair (quar*8+q) for j0 (.x) and j1 (.y).
            ulonglong2 ej[8];
#pragma unroll
            for (int q = 0; q < 8; q++)
                ej[q] = ETp2[(quar * 8 + q) * (N_LANG / 2) + ejb];

            // Tile A rows.
#pragma unroll
            for (int il = 0; il < 4; il++) {
                const ulonglong2* ei2 =
                    (const ulonglong2*)(s_negEi + il * D_EMB + quar * 16);
                ull a0 = acc[2 * il], a1 = acc[2 * il + 1];
#pragma unroll
                for (int q2 = 0; q2 < 4; q2++) {
                    ulonglong2 e = ei2[q2];             // broadcast LDS.128
                    a0 = f32x2_add(a0, f32x2_add(ej[2 * q2].x,     e.x) & ABSM);
                    a1 = f32x2_add(a1, f32x2_add(ej[2 * q2].y,     e.x) & ABSM);
                    a0 = f32x2_add(a0, f32x2_add(ej[2 * q2 + 1].x, e.y) & ABSM);
                    a1 = f32x2_add(a1, f32x2_add(ej[2 * q2 + 1].y, e.y) & ABSM);
                }
                acc[2 * il] = a0; acc[2 * il + 1] = a1;
            }
            // Tile B rows: top region only; reuses ej registers.
            if (hasB) {
#pragma unroll
                for (int il = 0; il < 4; il++) {
                    const ulonglong2* ei2 =
                        (const ulonglong2*)(s_negEi + (4 + il) * D_EMB + quar * 16);
                    ull a0 = acc[8 + 2 * il], a1 = acc[8 + 2 * il + 1];
#pragma unroll
                    for (int q2 = 0; q2 < 4; q2++) {
                        ulonglong2 e = ei2[q2];
                        a0 = f32x2_add(a0, f32x2_add(ej[2 * q2].x,     e.x) & ABSM);
                        a1 = f32x2_add(a1, f32x2_add(ej[2 * q2].y,     e.x) & ABSM);
                        a0 = f32x2_add(a0, f32x2_add(ej[2 * q2 + 1].x, e.y) & ABSM);
                        a1 = f32x2_add(a1, f32x2_add(ej[2 * q2 + 1].y, e.y) & ABSM);
                    }
                    acc[8 + 2 * il] = a0; acc[8 + 2 * il + 1] = a1;
                }
            }
        }

        // Epilogue: two j's per row.
#pragma unroll
        for (int il = 0; il < 4; il++) {
            union { ull u; float2 f; } c0, c1;
            c0.u = acc[2 * il]; c1.u = acc[2 * il + 1];
            float e0 = (c0.f.x + c0.f.y) * (1.0f / 64.0f);
            float e1 = (c1.f.x + c1.f.y) * (1.0f / 64.0f);
            float m0 = s_comb[il * V_VOC + idj0];
            float m1 = s_comb[il * V_VOC + idj1];
            int   ii = i0A + il, idi = s_id[il];
            if (j0     > ii && idi != idj0) { fsum += fabsf(e0 - m0); cnt++; }
            if (j0 + 1 > ii && idi != idj1) { fsum += fabsf(e1 - m1); cnt++; }
        }
        if (hasB) {
#pragma unroll
            for (int il = 0; il < 4; il++) {
                union { ull u; float2 f; } c0, c1;
                c0.u = acc[8 + 2 * il]; c1.u = acc[8 + 2 * il + 1];
                float e0 = (c0.f.x + c0.f.y) * (1.0f / 64.0f);
                float e1 = (c1.f.x + c1.f.y) * (1.0f / 64.0f);
                float m0 = s_comb[(4 + il) * V_VOC + idj0];
                float m1 = s_comb[(4 + il) * V_VOC + idj1];
                int   ii = i0B + il, idi = s_id[4 + il];
                if (j0     > ii && idi != idj0) { fsum += fabsf(e0 - m0); cnt++; }
                if (j0 + 1 > ii && idi != idj1) { fsum += fabsf(e1 - m1); cnt++; }
            }
        }
    }

    // Block reduction -> global double accumulator, then last-block finalize.
#pragma unroll
    for (int o = 16; o; o >>= 1) {
        fsum += __shfl_down_sync(0xffffffffu, fsum, o);
        cnt  += __shfl_down_sync(0xffffffffu, cnt, o);
    }
    __shared__ float    rs[8];
    __shared__ unsigned rc[8];
    if (lane == 0) { rs[warp] = fsum; rc[warp] = cnt; }
    __syncthreads();
    if (tid == 0) {
        float fs = 0.0f;
        unsigned cc = 0;
#pragma unroll
        for (int w = 0; w < 8; w++) { fs += rs[w]; cc += rc[w]; }
        atomicAdd(&g_sum, (double)fs);
        atomicAdd(&g_cnt, (unsigned long long)cc);
        __threadfence();
        unsigned ticket = atomicAdd(&g_done, 1u);
        if (ticket == NPAIR - 1) {
            out[0] = (float)(g_sum / (double)g_cnt);
            g_sum = 0.0;
            g_cnt = 0ull;
            g_max_bits = 0u;
            g_done = 0u;
        }
    }
}

// ---------------- launch ----------------
extern "C" void kernel_launch(void* const* d_in, const int* in_sizes, int n_in,
                              void* d_out, int out_size) {
    const int*   ids  = nullptr;
    const float* E    = nullptr;
    const float* tree = nullptr;
    const float* mapd = nullptr;
    for (int i = 0; i < n_in; i++) {
        int sz = in_sizes[i];
        if (sz == N_LANG)              ids = (const int*)d_in[i];
        else if (sz == N_LANG * D_EMB) E   = (const float*)d_in[i];
        else if (sz == V_VOC * V_VOC) {
            if (!tree) tree = (const float*)d_in[i];
            else       mapd = (const float*)d_in[i];
        }
    }
    float* out = (float*)d_out;

    const int SMEM_BYTES = (8 * V_VOC + 8 * D_EMB + 8) * (int)sizeof(float);
    cudaFuncSetAttribute(pair_kernel,
                         cudaFuncAttributeMaxDynamicSharedMemorySize, SMEM_BYTES);

    prep_kernel<<<576, 256>>>((const float4*)E, (const float4*)mapd);
    pair_kernel<<<NPAIR, 256, SMEM_BYTES>>>(ids, E, (const float4*)tree,
                                            (const float4*)mapd, out);
}

// round 15
// speedup vs baseline: 1.9139x; 1.0354x over previous
#include <cuda_runtime.h>
#include <cuda_bf16.h>

// N = 2048 languages, D = 64, V = 2048
#define N_LANG 2048
#define D_EMB  64
#define V_VOC  2048
#define NPAIR  256     // pair-kernel grid: block p owns rows 4p..4p+3 and 2044-4p..2047-4p

typedef unsigned long long ull;

// ---------------- device state (zero-init; pair kernel resets at end) --------
__device__ float2 g_ETp[(D_EMB / 2) * N_LANG];   // 512 KB transposed packed E
__device__ unsigned int       g_max_bits;
__device__ double             g_sum;
__device__ unsigned long long g_cnt;
__device__ unsigned int       g_done;

__device__ __forceinline__ ull f32x2_add(ull a, ull b) {
    ull r;
    asm("add.rn.f32x2 %0, %1, %2;" : "=l"(r) : "l"(a), "l"(b));
    return r;
}

// ---------------- kernel 1: fused prep (transpose || max) --------------------
// Blocks 0..63: tiled transpose E -> g_ETp (coalesced read AND write).
// Blocks 64..575: max(map_dist) with MLP-8 front-batched loads.
// map values >= 0 (avg of two uniforms) so uint-bit atomicMax is order-correct.
__global__ void prep_kernel(const float4* __restrict__ E4,
                            const float4* __restrict__ map4) {
    __shared__ float s[32][66];
    __shared__ float sm[8];
    const int t = threadIdx.x;

    if (blockIdx.x < 64) {
        const int b = blockIdx.x;            // 32 j-rows per block
#pragma unroll
        for (int r = 0; r < 2; r++) {
            int idx = r * 256 + t;
            int jl  = idx >> 4;
            int q   = idx & 15;
            float4 v = E4[(b * 32 + jl) * 16 + q];
            s[jl][q * 4 + 0] = v.x;
            s[jl][q * 4 + 1] = v.y;
            s[jl][q * 4 + 2] = v.z;
            s[jl][q * 4 + 3] = v.w;
        }
        __syncthreads();
        const int jl = t & 31;
#pragma unroll
        for (int k = 0; k < 4; k++) {
            int dp = (t >> 5) + 8 * k;
            g_ETp[dp * N_LANG + b * 32 + jl] =
                make_float2(s[jl][2 * dp], s[jl][2 * dp + 1]);
        }
    } else {
        const int idx = (blockIdx.x - 64) * 256 + t;   // 0 .. 131071
        float m = 0.0f;
#pragma unroll
        for (int k = 0; k < 8; k++) {
            float4 v = map4[idx + k * 131072];
            m = fmaxf(m, fmaxf(fmaxf(v.x, v.y), fmaxf(v.z, v.w)));
        }
#pragma unroll
        for (int o = 16; o; o >>= 1) m = fmaxf(m, __shfl_xor_sync(0xffffffffu, m, o));
        int wp = t >> 5;
        if ((t & 31) == 0) sm[wp] = m;
        __syncthreads();
        if (t == 0) {
            float bm = sm[0];
#pragma unroll
            for (int i = 1; i < 8; i++) bm = fmaxf(bm, sm[i]);
            atomicMax(&g_max_bits, __float_as_uint(bm));
        }
    }
}

// ---------------- kernel 2: triangular pair kernel + fused finalize ----------
// answer = sum_{i<j} |emb - metric| * [id_i != id_j] / count_{i<j} (factor 2 cancels).
// Block p owns tiles tA = rows 4p..4p+3 and tB = rows 2044-4p..2047-4p (spans sum
// ~const -> 256 balanced blocks at occupancy 2). Each lane handles TWO consecutive
// j's; ej loads are LDG.128 of transposed g_ETp, SOFTWARE-PIPELINED in 8 batches
// of 4 dim-pairs with ping-pong buffers (register-neutral vs the flat ej[8]):
// batch k+1's loads issue before batch k's compute, so each warp self-covers the
// ~250-cyc L2 latency. Combined metric rows (0.5*(tree+map*inv)) fused into 64KB
// smem during staging. Last block writes out and resets state.
__global__ void __launch_bounds__(256, 2)
pair_kernel(const int* __restrict__ ids, const float* __restrict__ E,
            const float4* __restrict__ tree4, const float4* __restrict__ map4,
            float* __restrict__ out) {
    extern __shared__ float smem[];
    float* s_comb  = smem;                           // 8 * 2048 floats (64 KB)
    float* s_negEi = smem + 8 * V_VOC;               // 8 * 64 floats  (2 KB)
    int*   s_id    = (int*)(s_negEi + 8 * D_EMB);    // 8 ints

    const int p   = blockIdx.x;
    const int i0A = 4 * p;
    const int i0B = N_LANG - 4 - 4 * p;   // 2044 - 4p
    const int tid = threadIdx.x;

    if (tid < 8) {
        int i = (tid < 4) ? (i0A + tid) : (i0B + tid - 4);
        s_id[tid] = ids[i];
    }
    __syncthreads();

    const float inv = 1.0f / __uint_as_float(g_max_bits);

    // Stage combined rows: 8 rows * 512 float4 = 4096 float4, 16 per thread.
    float4* s_comb4 = (float4*)s_comb;
#pragma unroll
    for (int r = 0; r < 16; r++) {
        int f4  = r * 256 + tid;
        int row = f4 >> 9;
        int col = f4 & 511;
        int id  = s_id[row];
        float4 t = tree4[id * (V_VOC / 4) + col];
        float4 m = map4[id * (V_VOC / 4) + col];
        float4 c;
        c.x = 0.5f * (t.x + m.x * inv);
        c.y = 0.5f * (t.y + m.y * inv);
        c.z = 0.5f * (t.z + m.z * inv);
        c.w = 0.5f * (t.w + m.w * inv);
        s_comb4[f4] = c;
    }
    // Negated E_i rows: 8 rows * 16 float4 = 128 float4.
    if (tid < 128) {
        int row = tid >> 4;
        int q   = tid & 15;
        int i   = (row < 4) ? (i0A + row) : (i0B + row - 4);
        float4 v = ((const float4*)E)[i * (D_EMB / 4) + q];
        float4 n;
        n.x = -v.x; n.y = -v.y; n.z = -v.z; n.w = -v.w;
        ((float4*)s_negEi)[row * (D_EMB / 4) + q] = n;
    }
    __syncthreads();

    const int warp = tid >> 5;
    const int lane = tid & 31;
    const int c0A  = i0A >> 6;            // chunks are 64 j wide
    const int c0B  = i0B >> 6;

    float    fsum = 0.0f;
    unsigned cnt  = 0;
    const ull ABSM = 0x7FFFFFFF7FFFFFFFull;
    const ulonglong2* ETp2 = (const ulonglong2*)g_ETp;

    for (int c = c0A + warp; c < N_LANG / 64; c += 8) {
        const int  j0   = c * 64 + 2 * lane;           // this lane's two j's
        const int  idj0 = __ldg(&ids[j0]);
        const int  idj1 = __ldg(&ids[j0 + 1]);
        const bool hasB = (c >= c0B);
        const int  ejb  = c * 32 + lane;               // ulonglong2 index base

        ull acc[16];                                    // [row 0..7][jslot 0..1]
#pragma unroll
        for (int r = 0; r < 16; r++) acc[r] = 0;

        // Software-pipelined mainloop: 8 batches of 4 dim-pairs, ping-pong bufs.
        ulonglong2 ea[4], eb[4];
#pragma unroll
        for (int q = 0; q < 4; q++)
            ea[q] = ETp2[q * (N_LANG / 2) + ejb];       // prefetch batch 0

#pragma unroll
        for (int bat = 0; bat < 8; bat++) {
            // Prefetch next batch into the other buffer.
            if (bat < 7) {
#pragma unroll
                for (int q = 0; q < 4; q++) {
                    ulonglong2 v = ETp2[((bat + 1) * 4 + q) * (N_LANG / 2) + ejb];
                    if (bat & 1) ea[q] = v; else eb[q] = v;
                }
            }
            ulonglong2 c0 = (bat & 1) ? eb[0] : ea[0];
            ulonglong2 c1 = (bat & 1) ? eb[1] : ea[1];
            ulonglong2 c2 = (bat & 1) ? eb[2] : ea[2];
            ulonglong2 c3 = (bat & 1) ? eb[3] : ea[3];

            // Tile A rows.
#pragma unroll
            for (int il = 0; il < 4; il++) {
                const ulonglong2* ei2 =
                    (const ulonglong2*)(s_negEi + il * D_EMB + bat * 8);
                ulonglong2 e01 = ei2[0];                // dim-pairs 4bat, 4bat+1
                ulonglong2 e23 = ei2[1];                // dim-pairs 4bat+2, 4bat+3
                ull a0 = acc[2 * il], a1 = acc[2 * il + 1];
                a0 = f32x2_add(a0, f32x2_add(c0.x, e01.x) & ABSM);
                a1 = f32x2_add(a1, f32x2_add(c0.y, e01.x) & ABSM);
                a0 = f32x2_add(a0, f32x2_add(c1.x, e01.y) & ABSM);
                a1 = f32x2_add(a1, f32x2_add(c1.y, e01.y) & ABSM);
                a0 = f32x2_add(a0, f32x2_add(c2.x, e23.x) & ABSM);
                a1 = f32x2_add(a1, f32x2_add(c2.y, e23.x) & ABSM);
                a0 = f32x2_add(a0, f32x2_add(c3.x, e23.y) & ABSM);
                a1 = f32x2_add(a1, f32x2_add(c3.y, e23.y) & ABSM);
                acc[2 * il] = a0; acc[2 * il + 1] = a1;
            }
            // Tile B rows: top region only; reuses the same ej batch.
            if (hasB) {
#pragma unroll
                for (int il = 0; il < 4; il++) {
                    const ulonglong2* ei2 =
                        (const ulonglong2*)(s_negEi + (4 + il) * D_EMB + bat * 8);
                    ulonglong2 e01 = ei2[0];
                    ulonglong2 e23 = ei2[1];
                    ull a0 = acc[8 + 2 * il], a1 = acc[8 + 2 * il + 1];
                    a0 = f32x2_add(a0, f32x2_add(c0.x, e01.x) & ABSM);
                    a1 = f32x2_add(a1, f32x2_add(c0.y, e01.x) & ABSM);
                    a0 = f32x2_add(a0, f32x2_add(c1.x, e01.y) & ABSM);
                    a1 = f32x2_add(a1, f32x2_add(c1.y, e01.y) & ABSM);
                    a0 = f32x2_add(a0, f32x2_add(c2.x, e23.x) & ABSM);
                    a1 = f32x2_add(a1, f32x2_add(c2.y, e23.x) & ABSM);
                    a0 = f32x2_add(a0, f32x2_add(c3.x, e23.y) & ABSM);
                    a1 = f32x2_add(a1, f32x2_add(c3.y, e23.y) & ABSM);
                    acc[8 + 2 * il] = a0; acc[8 + 2 * il + 1] = a1;
                }
            }
        }

        // Epilogue: two j's per row.
#pragma unroll
        for (int il = 0; il < 4; il++) {
            union { ull u; float2 f; } v0, v1;
            v0.u = acc[2 * il]; v1.u = acc[2 * il + 1];
            float e0 = (v0.f.x + v0.f.y) * (1.0f / 64.0f);
            float e1 = (v1.f.x + v1.f.y) * (1.0f / 64.0f);
            float m0 = s_comb[il * V_VOC + idj0];
            float m1 = s_comb[il * V_VOC + idj1];
            int   ii = i0A + il, idi = s_id[il];
            if (j0     > ii && idi != idj0) { fsum += fabsf(e0 - m0); cnt++; }
            if (j0 + 1 > ii && idi != idj1) { fsum += fabsf(e1 - m1); cnt++; }
        }
        if (hasB) {
#pragma unroll
            for (int il = 0; il < 4; il++) {
                union { ull u; float2 f; } v0, v1;
                v0.u = acc[8 + 2 * il]; v1.u = acc[8 + 2 * il + 1];
                float e0 = (v0.f.x + v0.f.y) * (1.0f / 64.0f);
                float e1 = (v1.f.x + v1.f.y) * (1.0f / 64.0f);
                float m0 = s_comb[(4 + il) * V_VOC + idj0];
                float m1 = s_comb[(4 + il) * V_VOC + idj1];
                int   ii = i0B + il, idi = s_id[4 + il];
                if (j0     > ii && idi != idj0) { fsum += fabsf(e0 - m0); cnt++; }
                if (j0 + 1 > ii && idi != idj1) { fsum += fabsf(e1 - m1); cnt++; }
            }
        }
    }

    // Block reduction -> global double accumulator, then last-block finalize.
#pragma unroll
    for (int o = 16; o; o >>= 1) {
        fsum += __shfl_down_sync(0xffffffffu, fsum, o);
        cnt  += __shfl_down_sync(0xffffffffu, cnt, o);
    }
    __shared__ float    rs[8];
    __shared__ unsigned rc[8];
    if (lane == 0) { rs[warp] = fsum; rc[warp] = cnt; }
    __syncthreads();
    if (tid == 0) {
        float fs = 0.0f;
        unsigned cc = 0;
#pragma unroll
        for (int w = 0; w < 8; w++) { fs += rs[w]; cc += rc[w]; }
        atomicAdd(&g_sum, (double)fs);
        atomicAdd(&g_cnt, (unsigned long long)cc);
        __threadfence();
        unsigned ticket = atomicAdd(&g_done, 1u);
        if (ticket == NPAIR - 1) {
            out[0] = (float)(g_sum / (double)g_cnt);
            g_sum = 0.0;
            g_cnt = 0ull;
            g_max_bits = 0u;
            g_done = 0u;
        }
    }
}

// ---------------- launch ----------------
extern "C" void kernel_launch(void* const* d_in, const int* in_sizes, int n_in,
                              void* d_out, int out_size) {
    const int*   ids  = nullptr;
    const float* E    = nullptr;
    const float* tree = nullptr;
    const float* mapd = nullptr;
    for (int i = 0; i < n_in; i++) {
        int sz = in_sizes[i];
        if (sz == N_LANG)              ids = (const int*)d_in[i];
        else if (sz == N_LANG * D_EMB) E   = (const float*)d_in[i];
        else if (sz == V_VOC * V_VOC) {
            if (!tree) tree = (const float*)d_in[i];
            else       mapd = (const float*)d_in[i];
        }
    }
    float* out = (float*)d_out;

    const int SMEM_BYTES = (8 * V_VOC + 8 * D_EMB + 8) * (int)sizeof(float);
    cudaFuncSetAttribute(pair_kernel,
                         cudaFuncAttributeMaxDynamicSharedMemorySize, SMEM_BYTES);

    prep_kernel<<<576, 256>>>((const float4*)E, (const float4*)mapd);
    pair_kernel<<<NPAIR, 256, SMEM_BYTES>>>(ids, E, (const float4*)tree,
                                            (const float4*)mapd, out);
}

// round 17
// speedup vs baseline: 1.9162x; 1.0012x over previous
#include <cuda_runtime.h>
#include <cuda_bf16.h>

// N = 2048 languages, D = 64, V = 2048
#define N_LANG 2048
#define D_EMB  64
#define V_VOC  2048
#define NPAIR  256     // pair-kernel grid: block p owns rows 4p..4p+3 and 2044-4p..2047-4p

typedef unsigned long long ull;

// ---------------- device state (zero-init; pair kernel resets at end) --------
__device__ float2 g_ETp[(D_EMB / 2) * N_LANG];   // 512 KB transposed packed E
__device__ unsigned int       g_max_bits;
__device__ double             g_sum;
__device__ unsigned long long g_cnt;
__device__ unsigned int       g_done;

__device__ __forceinline__ ull f32x2_add(ull a, ull b) {
    ull r;
    asm("add.rn.f32x2 %0, %1, %2;" : "=l"(r) : "l"(a), "l"(b));
    return r;
}

// ---------------- kernel 1: fused prep (transpose || max) --------------------
// Blocks 0..63: tiled transpose E -> g_ETp (coalesced read AND write).
// Blocks 64..575: max(map_dist) with MLP-8 front-batched loads.
// map values >= 0 (avg of two uniforms) so uint-bit atomicMax is order-correct.
__global__ void prep_kernel(const float4* __restrict__ E4,
                            const float4* __restrict__ map4) {
    __shared__ float s[32][66];
    __shared__ float sm[8];
    const int t = threadIdx.x;

    if (blockIdx.x < 64) {
        const int b = blockIdx.x;            // 32 j-rows per block
#pragma unroll
        for (int r = 0; r < 2; r++) {
            int idx = r * 256 + t;
            int jl  = idx >> 4;
            int q   = idx & 15;
            float4 v = E4[(b * 32 + jl) * 16 + q];
            s[jl][q * 4 + 0] = v.x;
            s[jl][q * 4 + 1] = v.y;
            s[jl][q * 4 + 2] = v.z;
            s[jl][q * 4 + 3] = v.w;
        }
        __syncthreads();
        const int jl = t & 31;
#pragma unroll
        for (int k = 0; k < 4; k++) {
            int dp = (t >> 5) + 8 * k;
            g_ETp[dp * N_LANG + b * 32 + jl] =
                make_float2(s[jl][2 * dp], s[jl][2 * dp + 1]);
        }
    } else {
        const int idx = (blockIdx.x - 64) * 256 + t;   // 0 .. 131071
        float m = 0.0f;
#pragma unroll
        for (int k = 0; k < 8; k++) {
            float4 v = map4[idx + k * 131072];
            m = fmaxf(m, fmaxf(fmaxf(v.x, v.y), fmaxf(v.z, v.w)));
        }
#pragma unroll
        for (int o = 16; o; o >>= 1) m = fmaxf(m, __shfl_xor_sync(0xffffffffu, m, o));
        int wp = t >> 5;
        if ((t & 31) == 0) sm[wp] = m;
        __syncthreads();
        if (t == 0) {
            float bm = sm[0];
#pragma unroll
            for (int i = 1; i < 8; i++) bm = fmaxf(bm, sm[i]);
            atomicMax(&g_max_bits, __float_as_uint(bm));
        }
    }
}

// ---------------- kernel 2: triangular pair kernel + fused finalize ----------
// answer = sum_{i<j} |emb - metric| * [id_i != id_j] / count_{i<j} (factor 2 cancels).
// Block p owns tiles tA = rows 4p..4p+3 and tB = rows 2044-4p..2047-4p.
// UNIFIED WORK QUEUE: items = A-chunks + B-chunks = (32-p/16) + (p/16+1) = 33 for
// EVERY block (perfect balance); warps stride the queue. One item = one 4-row tile
// x one 64-j chunk (2 j per lane) -> acc[8] + ej[4] keeps regs ~70, enabling
// OCCUPANCY 3 (24 warps/SM) to fill the issue slots that R14/R15 left 55% empty.
// ej: LDG.128 of transposed g_ETp (dim-pair for both j's). E_i negated in smem
// (broadcast LDS.128); combined metric rows (0.5*(tree+map*inv)) fused into 64KB
// smem during staging. Last block writes out and resets state.
__global__ void __launch_bounds__(256, 3)
pair_kernel(const int* __restrict__ ids, const float* __restrict__ E,
            const float4* __restrict__ tree4, const float4* __restrict__ map4,
            float* __restrict__ out) {
    extern __shared__ float smem[];
    float* s_comb  = smem;                           // 8 * 2048 floats (64 KB)
    float* s_negEi = smem + 8 * V_VOC;               // 8 * 64 floats  (2 KB)
    int*   s_id    = (int*)(s_negEi + 8 * D_EMB);    // 8 ints

    const int p   = blockIdx.x;
    const int i0A = 4 * p;
    const int i0B = N_LANG - 4 - 4 * p;   // 2044 - 4p
    const int tid = threadIdx.x;

    if (tid < 8) {
        int i = (tid < 4) ? (i0A + tid) : (i0B + tid - 4);
        s_id[tid] = ids[i];
    }
    __syncthreads();

    const float inv = 1.0f / __uint_as_float(g_max_bits);

    // Stage combined rows: 8 rows * 512 float4 = 4096 float4, 16 per thread.
    float4* s_comb4 = (float4*)s_comb;
#pragma unroll
    for (int r = 0; r < 16; r++) {
        int f4  = r * 256 + tid;
        int row = f4 >> 9;
        int col = f4 & 511;
        int id  = s_id[row];
        float4 t = tree4[id * (V_VOC / 4) + col];
        float4 m = map4[id * (V_VOC / 4) + col];
        float4 c;
        c.x = 0.5f * (t.x + m.x * inv);
        c.y = 0.5f * (t.y + m.y * inv);
        c.z = 0.5f * (t.z + m.z * inv);
        c.w = 0.5f * (t.w + m.w * inv);
        s_comb4[f4] = c;
    }
    // Negated E_i rows: 8 rows * 16 float4 = 128 float4.
    if (tid < 128) {
        int row = tid >> 4;
        int q   = tid & 15;
        int i   = (row < 4) ? (i0A + row) : (i0B + row - 4);
        float4 v = ((const float4*)E)[i * (D_EMB / 4) + q];
        float4 n;
        n.x = -v.x; n.y = -v.y; n.z = -v.z; n.w = -v.w;
        ((float4*)s_negEi)[row * (D_EMB / 4) + q] = n;
    }
    __syncthreads();

    const int warp  = tid >> 5;
    const int lane  = tid & 31;
    const int c0A   = i0A >> 6;            // chunks are 64 j wide
    const int c0B   = i0B >> 6;
    const int A_cnt = 32 - c0A;            // A items; total items = 33 always

    float    fsum = 0.0f;
    unsigned cnt  = 0;
    const ull ABSM = 0x7FFFFFFF7FFFFFFFull;
    const ulonglong2* ETp2 = (const ulonglong2*)g_ETp;

    for (int k = warp; k < 33; k += 8) {
        int c, rbase, ibase;
        if (k < A_cnt) { c = c0A + k;         rbase = 0; ibase = i0A; }
        else           { c = c0B + (k - A_cnt); rbase = 4; ibase = i0B; }

        const int j0   = c * 64 + 2 * lane;            // this lane's two j's
        const int idj0 = __ldg(&ids[j0]);
        const int idj1 = __ldg(&ids[j0 + 1]);
        const int ejb  = c * 32 + lane;                // ulonglong2 index base

        ull acc[8];                                     // [row 0..3][jslot 0..1]
#pragma unroll
        for (int r = 0; r < 8; r++) acc[r] = 0;

#pragma unroll
        for (int oct = 0; oct < 8; oct++) {
            // 4 coalesced LDG.128: dim-pairs oct*4..oct*4+3 for j0 (.x) and j1 (.y).
            ulonglong2 ej[4];
#pragma unroll
            for (int q = 0; q < 4; q++)
                ej[q] = ETp2[(oct * 4 + q) * (N_LANG / 2) + ejb];

#pragma unroll
            for (int il = 0; il < 4; il++) {
                const ulonglong2* ei2 =
                    (const ulonglong2*)(s_negEi + (rbase + il) * D_EMB + oct * 8);
                ulonglong2 e01 = ei2[0];               // dim-pairs oct*4, oct*4+1
                ulonglong2 e23 = ei2[1];               // dim-pairs oct*4+2, oct*4+3
                ull a0 = acc[2 * il], a1 = acc[2 * il + 1];
                a0 = f32x2_add(a0, f32x2_add(ej[0].x, e01.x) & ABSM);
                a1 = f32x2_add(a1, f32x2_add(ej[0].y, e01.x) & ABSM);
                a0 = f32x2_add(a0, f32x2_add(ej[1].x, e01.y) & ABSM);
                a1 = f32x2_add(a1, f32x2_add(ej[1].y, e01.y) & ABSM);
                a0 = f32x2_add(a0, f32x2_add(ej[2].x, e23.x) & ABSM);
                a1 = f32x2_add(a1, f32x2_add(ej[2].y, e23.x) & ABSM);
                a0 = f32x2_add(a0, f32x2_add(ej[3].x, e23.y) & ABSM);
                a1 = f32x2_add(a1, f32x2_add(ej[3].y, e23.y) & ABSM);
                acc[2 * il] = a0; acc[2 * il + 1] = a1;
            }
        }

        // Epilogue: two j's per row.
#pragma unroll
        for (int il = 0; il < 4; il++) {
            union { ull u; float2 f; } v0, v1;
            v0.u = acc[2 * il]; v1.u = acc[2 * il + 1];
            float e0 = (v0.f.x + v0.f.y) * (1.0f / 64.0f);
            float e1 = (v1.f.x + v1.f.y) * (1.0f / 64.0f);
            float m0 = s_comb[(rbase + il) * V_VOC + idj0];
            float m1 = s_comb[(rbase + il) * V_VOC + idj1];
            int   ii  = ibase + il;
            int   idi = s_id[rbase + il];
            if (j0     > ii && idi != idj0) { fsum += fabsf(e0 - m0); cnt++; }
            if (j0 + 1 > ii && idi != idj1) { fsum += fabsf(e1 - m1); cnt++; }
        }
    }

    // Block reduction -> global double accumulator, then last-block finalize.
#pragma unroll
    for (int o = 16; o; o >>= 1) {
        fsum += __shfl_down_sync(0xffffffffu, fsum, o);
        cnt  += __shfl_down_sync(0xffffffffu, cnt, o);
    }
    __shared__ float    rs[8];
    __shared__ unsigned rc[8];
    if (lane == 0) { rs[warp] = fsum; rc[warp] = cnt; }
    __syncthreads();
    if (tid == 0) {
        float fs = 0.0f;
        unsigned cc = 0;
#pragma unroll
        for (int w = 0; w < 8; w++) { fs += rs[w]; cc += rc[w]; }
        atomicAdd(&g_sum, (double)fs);
        atomicAdd(&g_cnt, (unsigned long long)cc);
        __threadfence();
        unsigned ticket = atomicAdd(&g_done, 1u);
        if (ticket == NPAIR - 1) {
            out[0] = (float)(g_sum / (double)g_cnt);
            g_sum = 0.0;
            g_cnt = 0ull;
            g_max_bits = 0u;
            g_done = 0u;
        }
    }
}

// ---------------- launch ----------------
extern "C" void kernel_launch(void* const* d_in, const int* in_sizes, int n_in,
                              void* d_out, int out_size) {
    const int*   ids  = nullptr;
    const float* E    = nullptr;
    const float* tree = nullptr;
    const float* mapd = nullptr;
    for (int i = 0; i < n_in; i++) {
        int sz = in_sizes[i];
        if (sz == N_LANG)              ids = (const int*)d_in[i];
        else if (sz == N_LANG * D_EMB) E   = (const float*)d_in[i];
        else if (sz == V_VOC * V_VOC) {
            if (!tree) tree = (const float*)d_in[i];
            else       mapd = (const float*)d_in[i];
        }
    }
    float* out = (float*)d_out;

    const int SMEM_BYTES = (8 * V_VOC + 8 * D_EMB + 8) * (int)sizeof(float);
    cudaFuncSetAttribute(pair_kernel,
                         cudaFuncAttributeMaxDynamicSharedMemorySize, SMEM_BYTES);

    prep_kernel<<<576, 256>>>((const float4*)E, (const float4*)mapd);
    pair_kernel<<<NPAIR, 256, SMEM_BYTES>>>(ids, E, (const float4*)tree,
                                            (const float4*)mapd, out);
}